// round 8
// baseline (speedup 1.0000x reference)
#include <cuda_runtime.h>
#include <cuda_bf16.h>
#include <math.h>
#include <stdint.h>

#define Tn  2048
#define Dm  1024
#define FFm 4096
#define Vv  32000
#define Bm  2
#define Sm  1024
#define Hm  16
#define Lm  6

typedef __nv_bfloat16 bf16;

// ---------------- scratch (static device globals; no allocation) ------------
__device__ float g_x  [Tn * Dm];
__device__ bf16  g_hh [Tn * Dm];
__device__ bf16  g_hl [Tn * Dm];
__device__ float g_q  [Tn * Dm];
__device__ float g_k  [Tn * Dm];
__device__ float g_v  [Tn * Dm];
__device__ bf16  g_ah [Tn * Dm];
__device__ bf16  g_al [Tn * Dm];
__device__ float g_gate[(long)Tn * FFm];
__device__ float g_up  [(long)Tn * FFm];
__device__ bf16  g_gh [(long)Tn * FFm];
__device__ bf16  g_gl [(long)Tn * FFm];

// bf16 ternary weight caches
__device__ bf16 g_wq[(long)Lm * Dm * Dm];
__device__ bf16 g_wk[(long)Lm * Dm * Dm];
__device__ bf16 g_wv[(long)Lm * Dm * Dm];
__device__ bf16 g_wo[(long)Lm * Dm * Dm];
__device__ bf16 g_wg[(long)Lm * FFm * Dm];
__device__ bf16 g_wu[(long)Lm * FFm * Dm];
__device__ bf16 g_wd[(long)Lm * FFm * Dm];
__device__ bf16 g_wh[(long)Vv * Dm];

__device__ __forceinline__ void split_bf16(float v, bf16& hi, bf16& lo) {
    hi = __float2bfloat16(v);
    lo = __float2bfloat16(v - __bfloat162float(hi));
}
__device__ __forceinline__ void cp_async16(uint32_t dst, const void* src) {
    asm volatile("cp.async.cg.shared.global [%0], [%1], 16;" :: "r"(dst), "l"(src));
}
__device__ __forceinline__ void cp_commit() {
    asm volatile("cp.async.commit_group;");
}
__device__ __forceinline__ uint32_t smem_u32(const void* p) {
    return (uint32_t)__cvta_generic_to_shared(p);
}
__device__ __forceinline__ void ldsm_x4(uint32_t* r, uint32_t addr) {
    asm volatile("ldmatrix.sync.aligned.m8n8.x4.shared.b16 {%0,%1,%2,%3}, [%4];"
                 : "=r"(r[0]), "=r"(r[1]), "=r"(r[2]), "=r"(r[3]) : "r"(addr));
}
__device__ __forceinline__ void mma_bf16(float* d, const uint32_t* a,
                                         const uint32_t* b) {
    asm volatile(
        "mma.sync.aligned.m16n8k16.row.col.f32.bf16.bf16.f32 "
        "{%0,%1,%2,%3}, {%4,%5,%6,%7}, {%8,%9}, {%0,%1,%2,%3};"
        : "+f"(d[0]), "+f"(d[1]), "+f"(d[2]), "+f"(d[3])
        : "r"(a[0]), "r"(a[1]), "r"(a[2]), "r"(a[3]), "r"(b[0]), "r"(b[1]));
}

// ---------------- single-launch weight fp32 -> bf16 --------------------------
struct WAll {
    const float* src[8];
    bf16*        dst[8];
    long         cum[9];   // cumulative sizes in 4-element units
};
__global__ void w2b_all_kernel(WAll wa) {
    long i4 = (long)blockIdx.x * blockDim.x + threadIdx.x;
    if (i4 >= wa.cum[8]) return;
    int seg = 0;
    #pragma unroll
    for (int s = 0; s < 7; s++) if (i4 >= wa.cum[s + 1]) seg = s + 1;
    long li = (i4 - wa.cum[seg]) * 4;
    float4 v = *(const float4*)&wa.src[seg][li];
    bf16* d = wa.dst[seg];
    *(__nv_bfloat162*)&d[li]     = __floats2bfloat162_rn(v.x, v.y);
    *(__nv_bfloat162*)&d[li + 2] = __floats2bfloat162_rn(v.z, v.w);
}

// ---------------- embedding + positional ------------------------------------
__global__ void embed_kernel(const int* __restrict__ ids,
                             const float* __restrict__ et,
                             const float* __restrict__ es,
                             const float* __restrict__ pe,
                             float* __restrict__ x) {
    int t  = blockIdx.x;
    int id = ids[t];
    int s  = t % Sm;
    for (int d = threadIdx.x; d < Dm; d += blockDim.x) {
        long wi = (long)id * Dm + d;
        x[(long)t * Dm + d] = et[wi] * es[wi >> 7] + pe[s * Dm + d];
    }
}

// ---------------- RMSNorm -> hi/lo bf16 --------------------------------------
__global__ void rms_kernel(const float* __restrict__ X,
                           const float* __restrict__ w,
                           bf16* __restrict__ Yh, bf16* __restrict__ Yl) {
    int t = blockIdx.x, tid = threadIdx.x;
    __shared__ float red[256];
    float s = 0.f;
    for (int d = tid; d < Dm; d += 256) {
        float v = X[(long)t * Dm + d];
        s += v * v;
    }
    red[tid] = s; __syncthreads();
    for (int o = 128; o > 0; o >>= 1) {
        if (tid < o) red[tid] += red[tid + o];
        __syncthreads();
    }
    float r = rsqrtf(red[0] / Dm + 1e-6f);
    for (int d = tid; d < Dm; d += 256) {
        float v = X[(long)t * Dm + d] * r * w[d];
        bf16 hi, lo; split_bf16(v, hi, lo);
        Yh[(long)t * Dm + d] = hi;
        Yl[(long)t * Dm + d] = lo;
    }
}

// ---------------- 2-pass GEMM, 128x128 tile, 3-stage pipeline ----------------
#define SAS 72
#define A_ELE (128 * SAS)
#define STAGE_E (3 * A_ELE)                            // Ah, Al, W
#define GEMM_SMEM (3 * STAGE_E * (int)sizeof(bf16))    // 165888

__device__ __forceinline__ void gemm_core(const bf16* __restrict__ Xh,
                                          const bf16* __restrict__ Xl,
                                          const bf16* __restrict__ W,
                                          const float* __restrict__ Sc,
                                          const float* __restrict__ res,
                                          float* __restrict__ Y,
                                          int R, int IN, int bm, int bn) {
    extern __shared__ bf16 smp[];

    const int tid  = threadIdx.x;
    const int warp = tid >> 5, lane = tid & 31;
    const int warpM = warp & 3, warpN = warp >> 2;
    const int groups = IN >> 7;
    const int lr = lane >> 2;
    const int lc = (lane & 3) << 1;
    const int lrow  = lane & 15;
    const int lcol8 = (lane >> 4) << 3;

    float master[2][4][4];
    float temp  [2][4][4];
    #pragma unroll
    for (int a = 0; a < 2; a++)
        #pragma unroll
        for (int b = 0; b < 4; b++)
            #pragma unroll
            for (int c = 0; c < 4; c++) { master[a][b][c] = 0.f; temp[a][b][c] = 0.f; }

    const int nIter = IN >> 6;

    auto load_stage = [&](int st, int it) {
        bf16* ah = smp + st * STAGE_E;
        bf16* al = ah + A_ELE;
        bf16* ws = al + A_ELE;
        int k0 = it << 6;
        #pragma unroll
        for (int p = 0; p < 2; p++) {
            int idx = tid + p * 512;
            int m = idx >> 3, c8 = (idx & 7) << 3;
            long gi = (long)(bm + m) * IN + k0 + c8;
            cp_async16(smem_u32(ah + m * SAS + c8), Xh + gi);
            cp_async16(smem_u32(al + m * SAS + c8), Xl + gi);
            cp_async16(smem_u32(ws + m * SAS + c8), W + (long)(bn + m) * IN + k0 + c8);
        }
    };

    load_stage(0, 0); cp_commit();
    load_stage(1, 1); cp_commit();

    for (int it = 0; it < nIter; it++) {
        if (it + 1 < nIter) asm volatile("cp.async.wait_group 1;");
        else                asm volatile("cp.async.wait_group 0;");
        __syncthreads();

        if (it + 2 < nIter) { load_stage((it + 2) % 3, it + 2); cp_commit(); }

        const int st = it % 3;
        const bf16* ah = smp + st * STAGE_E;
        const bf16* al = ah + A_ELE;
        const bf16* ws = al + A_ELE;

        #pragma unroll
        for (int ks = 0; ks < 4; ks++) {
            const int kb = ks * 16;
            uint32_t fah[2][4], fal[2][4], fb[4][2];
            #pragma unroll
            for (int mt = 0; mt < 2; mt++) {
                int m0 = warpM * 32 + mt * 16;
                ldsm_x4(fah[mt], smem_u32(ah + (m0 + lrow) * SAS + kb + lcol8));
                ldsm_x4(fal[mt], smem_u32(al + (m0 + lrow) * SAS + kb + lcol8));
            }
            #pragma unroll
            for (int np = 0; np < 2; np++) {
                int n0 = warpN * 32 + np * 16;
                uint32_t q[4];
                ldsm_x4(q, smem_u32(ws + (n0 + lrow) * SAS + kb + lcol8));
                fb[np * 2][0] = q[0];     fb[np * 2][1] = q[2];
                fb[np * 2 + 1][0] = q[1]; fb[np * 2 + 1][1] = q[3];
            }
            #pragma unroll
            for (int mt = 0; mt < 2; mt++)
                #pragma unroll
                for (int nt = 0; nt < 4; nt++) {
                    mma_bf16(temp[mt][nt], fah[mt], fb[nt]);
                    mma_bf16(temp[mt][nt], fal[mt], fb[nt]);
                }
        }

        if (it & 1) {   // 128-K group boundary
            int g = it >> 1;
            #pragma unroll
            for (int nt = 0; nt < 4; nt++) {
                int r0 = bn + warpN * 32 + nt * 8 + lc;
                float s0 = __ldg(&Sc[(long)r0 * groups + g]);
                float s1 = __ldg(&Sc[(long)(r0 + 1) * groups + g]);
                #pragma unroll
                for (int mt = 0; mt < 2; mt++) {
                    master[mt][nt][0] += s0 * temp[mt][nt][0];
                    master[mt][nt][1] += s1 * temp[mt][nt][1];
                    master[mt][nt][2] += s0 * temp[mt][nt][2];
                    master[mt][nt][3] += s1 * temp[mt][nt][3];
                    temp[mt][nt][0] = 0.f; temp[mt][nt][1] = 0.f;
                    temp[mt][nt][2] = 0.f; temp[mt][nt][3] = 0.f;
                }
            }
        }
    }

    #pragma unroll
    for (int mt = 0; mt < 2; mt++) {
        int m0 = bm + warpM * 32 + mt * 16 + lr;
        #pragma unroll
        for (int nt = 0; nt < 4; nt++) {
            int r0 = bn + warpN * 32 + nt * 8 + lc;
            float2 v0 = make_float2(master[mt][nt][0], master[mt][nt][1]);
            float2 v1 = make_float2(master[mt][nt][2], master[mt][nt][3]);
            if (res) {
                float2 p0 = *(const float2*)&res[(long)m0 * R + r0];
                float2 p1 = *(const float2*)&res[(long)(m0 + 8) * R + r0];
                v0.x += p0.x; v0.y += p0.y;
                v1.x += p1.x; v1.y += p1.y;
            }
            *(float2*)&Y[(long)m0 * R + r0]       = v0;
            *(float2*)&Y[(long)(m0 + 8) * R + r0] = v1;
        }
    }
}

__global__ void __launch_bounds__(512)
gemm_kernel(const bf16* __restrict__ Xh, const bf16* __restrict__ Xl,
            const bf16* __restrict__ W, const float* __restrict__ Sc,
            const float* __restrict__ res, float* __restrict__ Y,
            int R, int IN) {
    gemm_core(Xh, Xl, W, Sc, res, Y, R, IN, blockIdx.y * 128, blockIdx.x * 128);
}

struct GB3 {
    const bf16 *w0, *w1, *w2;
    const float *s0, *s1, *s2;
    float *y0, *y1, *y2;
};
__global__ void __launch_bounds__(512)
gemm_batch(const bf16* __restrict__ Xh, const bf16* __restrict__ Xl,
           GB3 gb, int R, int IN) {
    int z = blockIdx.z;
    const bf16*  W  = (z == 0) ? gb.w0 : (z == 1) ? gb.w1 : gb.w2;
    const float* Sc = (z == 0) ? gb.s0 : (z == 1) ? gb.s1 : gb.s2;
    float*       Y  = (z == 0) ? gb.y0 : (z == 1) ? gb.y1 : gb.y2;
    gemm_core(Xh, Xl, W, Sc, nullptr, Y, R, IN, blockIdx.y * 128, blockIdx.x * 128);
}

// ---------------- balanced flash attention (float4-vectorized) ---------------
#define AST 68
#define ATTN_SMEM (4 * 64 * AST * (int)sizeof(float))   // 69632

__global__ void __launch_bounds__(128)
attn_flash_kernel(const float* __restrict__ Q,
                  const float* __restrict__ K,
                  const float* __restrict__ V,
                  const bf16* __restrict__ Hh,
                  const bf16* __restrict__ Hl,
                  const float* __restrict__ alpha,
                  int layer,
                  bf16* __restrict__ Oh, bf16* __restrict__ Ol) {
    extern __shared__ float sm[];
    float* sQ = sm;
    float* sK = sm + 64 * AST;
    float* sV = sm + 2 * 64 * AST;
    float* sP = sm + 3 * 64 * AST;

    const int nQT = Sm / 64;
    const int h = blockIdx.y, b = blockIdx.z;
    const int tid = threadIdx.x, w = tid >> 5, ln = tid & 31;
    const int ry = ln >> 3, cx = ln & 7;
    const int row0 = w * 16 + ry * 4;
    const int hoff = h * 64;

    #pragma unroll
    for (int pass = 0; pass < 2; pass++) {
        const int qt = (pass == 0) ? blockIdx.x : (nQT - 1 - blockIdx.x);
        const long tok0 = (long)b * Sm + qt * 64;

        __syncthreads();
        for (int i = tid; i < 64 * 16; i += 128) {
            int r = i >> 4, c4 = (i & 15) << 2;
            *(float4*)&sQ[r * AST + c4] =
                *(const float4*)&Q[(tok0 + r) * Dm + hoff + c4];
        }

        float m[4], l[4], acc[4][8];
        #pragma unroll
        for (int r = 0; r < 4; r++) {
            m[r] = -1e30f; l[r] = 0.f;
            #pragma unroll
            for (int d = 0; d < 8; d++) acc[r][d] = 0.f;
        }

        const int nkt = qt + 1;
        for (int kt = 0; kt < nkt; kt++) {
            __syncthreads();
            long kbase = (long)b * Sm + kt * 64;
            for (int i = tid; i < 64 * 16; i += 128) {
                int r = i >> 4, c4 = (i & 15) << 2;
                *(float4*)&sK[r * AST + c4] =
                    *(const float4*)&K[(kbase + r) * Dm + hoff + c4];
                *(float4*)&sV[r * AST + c4] =
                    *(const float4*)&V[(kbase + r) * Dm + hoff + c4];
            }
            __syncthreads();

            // ---- QK^T (float4 inner loop)
            float s[4][8];
            #pragma unroll
            for (int r = 0; r < 4; r++)
                #pragma unroll
                for (int c = 0; c < 8; c++) s[r][c] = 0.f;
            for (int d0 = 0; d0 < 64; d0 += 4) {
                float qv[4][4], kv[8][4];
                #pragma unroll
                for (int r = 0; r < 4; r++) {
                    float4 q4 = *(const float4*)&sQ[(row0 + r) * AST + d0];
                    qv[r][0] = q4.x; qv[r][1] = q4.y; qv[r][2] = q4.z; qv[r][3] = q4.w;
                }
                #pragma unroll
                for (int c = 0; c < 8; c++) {
                    float4 k4 = *(const float4*)&sK[(cx * 8 + c) * AST + d0];
                    kv[c][0] = k4.x; kv[c][1] = k4.y; kv[c][2] = k4.z; kv[c][3] = k4.w;
                }
                #pragma unroll
                for (int r = 0; r < 4; r++)
                    #pragma unroll
                    for (int c = 0; c < 8; c++)
                        #pragma unroll
                        for (int dd = 0; dd < 4; dd++)
                            s[r][c] = fmaf(qv[r][dd], kv[c][dd], s[r][c]);
            }
            const bool diag = (kt == qt);
            #pragma unroll
            for (int r = 0; r < 4; r++)
                #pragma unroll
                for (int c = 0; c < 8; c++) {
                    s[r][c] *= 0.125f;
                    if (diag && (cx * 8 + c > row0 + r)) s[r][c] = -1e30f;
                }

            // ---- online softmax
            #pragma unroll
            for (int r = 0; r < 4; r++) {
                float mn = s[r][0];
                #pragma unroll
                for (int c = 1; c < 8; c++) mn = fmaxf(mn, s[r][c]);
                #pragma unroll
                for (int o = 1; o < 8; o <<= 1)
                    mn = fmaxf(mn, __shfl_xor_sync(0xffffffffu, mn, o));
                mn = fmaxf(mn, m[r]);
                float fac = expf(m[r] - mn);
                m[r] = mn;
                float p8[8], ls = 0.f;
                #pragma unroll
                for (int c = 0; c < 8; c++) {
                    p8[c] = expf(s[r][c] - mn);
                    ls += p8[c];
                }
                *(float4*)&sP[(row0 + r) * AST + cx * 8] =
                    make_float4(p8[0], p8[1], p8[2], p8[3]);
                *(float4*)&sP[(row0 + r) * AST + cx * 8 + 4] =
                    make_float4(p8[4], p8[5], p8[6], p8[7]);
                #pragma unroll
                for (int o = 1; o < 8; o <<= 1)
                    ls += __shfl_xor_sync(0xffffffffu, ls, o);
                l[r] = l[r] * fac + ls;
                #pragma unroll
                for (int d = 0; d < 8; d++) acc[r][d] *= fac;
            }
            __syncwarp();

            // ---- PV (float4 inner loop)
            for (int j0 = 0; j0 < 64; j0 += 4) {
                float pr[4][4], vv[4][8];
                #pragma unroll
                for (int r = 0; r < 4; r++) {
                    float4 p4 = *(const float4*)&sP[(row0 + r) * AST + j0];
                    pr[r][0] = p4.x; pr[r][1] = p4.y; pr[r][2] = p4.z; pr[r][3] = p4.w;
                }
                #pragma unroll
                for (int jj = 0; jj < 4; jj++) {
                    float4 a = *(const float4*)&sV[(j0 + jj) * AST + cx * 8];
                    float4 bq = *(const float4*)&sV[(j0 + jj) * AST + cx * 8 + 4];
                    vv[jj][0] = a.x;  vv[jj][1] = a.y;  vv[jj][2] = a.z;  vv[jj][3] = a.w;
                    vv[jj][4] = bq.x; vv[jj][5] = bq.y; vv[jj][6] = bq.z; vv[jj][7] = bq.w;
                }
                #pragma unroll
                for (int r = 0; r < 4; r++)
                    #pragma unroll
                    for (int jj = 0; jj < 4; jj++)
                        #pragma unroll
                        for (int d = 0; d < 8; d++)
                            acc[r][d] = fmaf(pr[r][jj], vv[jj][d], acc[r][d]);
            }
            __syncwarp();
        }

        float a = alpha[layer * Hm + h];
        #pragma unroll
        for (int r = 0; r < 4; r++) {
            float inv = 1.f / l[r];
            long t = tok0 + row0 + r;
            #pragma unroll
            for (int d = 0; d < 8; d++) {
                long oi = t * Dm + hoff + cx * 8 + d;
                float hn = __bfloat162float(Hh[oi]) + __bfloat162float(Hl[oi]);
                float v = acc[r][d] * inv + a * hn;
                bf16 hi, lo; split_bf16(v, hi, lo);
                Oh[oi] = hi; Ol[oi] = lo;
            }
        }
    }
}

// ---------------- SiLU(gate) * up -> hi/lo bf16 (float4) ---------------------
__global__ void silu_mul_kernel(const float* __restrict__ g,
                                const float* __restrict__ u,
                                bf16* __restrict__ Yh, bf16* __restrict__ Yl,
                                long n4) {
    long i = ((long)blockIdx.x * blockDim.x + threadIdx.x);
    if (i < n4) {
        long b = i * 4;
        float4 gv = *(const float4*)&g[b];
        float4 uv = *(const float4*)&u[b];
        float v0 = (gv.x / (1.f + expf(-gv.x))) * uv.x;
        float v1 = (gv.y / (1.f + expf(-gv.y))) * uv.y;
        float v2 = (gv.z / (1.f + expf(-gv.z))) * uv.z;
        float v3 = (gv.w / (1.f + expf(-gv.w))) * uv.w;
        bf16 h0, l0, h1, l1, h2, l2, h3, l3;
        split_bf16(v0, h0, l0); split_bf16(v1, h1, l1);
        split_bf16(v2, h2, l2); split_bf16(v3, h3, l3);
        *(__nv_bfloat162*)&Yh[b]     = __nv_bfloat162(h0, h1);
        *(__nv_bfloat162*)&Yh[b + 2] = __nv_bfloat162(h2, h3);
        *(__nv_bfloat162*)&Yl[b]     = __nv_bfloat162(l0, l1);
        *(__nv_bfloat162*)&Yl[b + 2] = __nv_bfloat162(l2, l3);
    }
}

// =============================================================================
extern "C" void kernel_launch(void* const* d_in, const int* in_sizes, int n_in,
                              void* d_out, int out_size) {
    const int*   ids    = (const int*)  d_in[0];
    const float* emb_t  = (const float*)d_in[1];
    const float* emb_s  = (const float*)d_in[2];
    const float* pos    = (const float*)d_in[3];
    const float* q_t    = (const float*)d_in[4];
    const float* q_s    = (const float*)d_in[5];
    const float* k_t    = (const float*)d_in[6];
    const float* k_s    = (const float*)d_in[7];
    const float* v_t    = (const float*)d_in[8];
    const float* v_s    = (const float*)d_in[9];
    const float* o_t    = (const float*)d_in[10];
    const float* o_s    = (const float*)d_in[11];
    const float* gt     = (const float*)d_in[12];
    const float* gs     = (const float*)d_in[13];
    const float* ut     = (const float*)d_in[14];
    const float* us     = (const float*)d_in[15];
    const float* dt     = (const float*)d_in[16];
    const float* ds     = (const float*)d_in[17];
    const float* alpha  = (const float*)d_in[18];
    const float* na_w   = (const float*)d_in[19];
    const float* nm_w   = (const float*)d_in[20];
    const float* nf_w   = (const float*)d_in[21];
    const float* head_t = (const float*)d_in[22];
    const float* head_s = (const float*)d_in[23];

    float *x, *q, *k, *v, *gate, *up;
    bf16 *hh, *hl, *ah, *al, *gh, *gl;
    bf16 *wq, *wk, *wv, *wo, *wg, *wu, *wd, *wh;
    cudaGetSymbolAddress((void**)&x,    g_x);
    cudaGetSymbolAddress((void**)&hh,   g_hh);
    cudaGetSymbolAddress((void**)&hl,   g_hl);
    cudaGetSymbolAddress((void**)&q,    g_q);
    cudaGetSymbolAddress((void**)&k,    g_k);
    cudaGetSymbolAddress((void**)&v,    g_v);
    cudaGetSymbolAddress((void**)&ah,   g_ah);
    cudaGetSymbolAddress((void**)&al,   g_al);
    cudaGetSymbolAddress((void**)&gate, g_gate);
    cudaGetSymbolAddress((void**)&up,   g_up);
    cudaGetSymbolAddress((void**)&gh,   g_gh);
    cudaGetSymbolAddress((void**)&gl,   g_gl);
    cudaGetSymbolAddress((void**)&wq,   g_wq);
    cudaGetSymbolAddress((void**)&wk,   g_wk);
    cudaGetSymbolAddress((void**)&wv,   g_wv);
    cudaGetSymbolAddress((void**)&wo,   g_wo);
    cudaGetSymbolAddress((void**)&wg,   g_wg);
    cudaGetSymbolAddress((void**)&wu,   g_wu);
    cudaGetSymbolAddress((void**)&wd,   g_wd);
    cudaGetSymbolAddress((void**)&wh,   g_wh);

    const long sQsz = (long)Dm * Dm / 128;
    const long sFsz = (long)Dm * FFm / 128;
    const long nD = (long)Lm * Dm * Dm;
    const long nF = (long)Lm * FFm * Dm;
    const long nH = (long)Vv * Dm;

    static bool attr_done = false;
    if (!attr_done) {
        cudaFuncSetAttribute(gemm_kernel,
                             cudaFuncAttributeMaxDynamicSharedMemorySize, GEMM_SMEM);
        cudaFuncSetAttribute(gemm_batch,
                             cudaFuncAttributeMaxDynamicSharedMemorySize, GEMM_SMEM);
        cudaFuncSetAttribute(attn_flash_kernel,
                             cudaFuncAttributeMaxDynamicSharedMemorySize, ATTN_SMEM);
        attr_done = true;
    }

    // ---- single-launch weight conversion ----
    {
        WAll wa;
        const float* srcs[8] = {q_t, k_t, v_t, o_t, gt, ut, dt, head_t};
        bf16* dsts[8]        = {wq,  wk,  wv,  wo,  wg, wu, wd, wh};
        long  szs[8]         = {nD,  nD,  nD,  nD,  nF, nF, nF, nH};
        long c = 0;
        wa.cum[0] = 0;
        for (int i = 0; i < 8; i++) {
            wa.src[i] = srcs[i]; wa.dst[i] = dsts[i];
            c += szs[i] / 4; wa.cum[i + 1] = c;
        }
        w2b_all_kernel<<<(unsigned)((c + 255) / 256), 256>>>(wa);
    }

    embed_kernel<<<Tn, 256>>>(ids, emb_t, emb_s, pos, x);

    dim3 gD(Dm / 128,  Tn / 128);        // 128
    dim3 gQKV(Dm / 128, Tn / 128, 3);    // 384
    dim3 gGU(FFm / 128, Tn / 128, 2);    // 1024
    dim3 gVg(Vv / 128, Tn / 128);        // 4000
    dim3 ga(Sm / 128, Hm, Bm);           // 256 balanced blocks

    for (int l = 0; l < Lm; l++) {
        long oD = (long)l * Dm * Dm;
        long oF = (long)l * FFm * Dm;

        rms_kernel<<<Tn, 256>>>(x, na_w + l * Dm, hh, hl);

        GB3 qkv;
        qkv.w0 = wq + oD; qkv.s0 = q_s + l * sQsz; qkv.y0 = q;
        qkv.w1 = wk + oD; qkv.s1 = k_s + l * sQsz; qkv.y1 = k;
        qkv.w2 = wv + oD; qkv.s2 = v_s + l * sQsz; qkv.y2 = v;
        gemm_batch<<<gQKV, 512, GEMM_SMEM>>>(hh, hl, qkv, Dm, Dm);

        attn_flash_kernel<<<ga, 128, ATTN_SMEM>>>(q, k, v, hh, hl, alpha, l, ah, al);

        gemm_kernel<<<gD, 512, GEMM_SMEM>>>(ah, al, wo + oD, o_s + l * sQsz,
                                            x, x, Dm, Dm);

        rms_kernel<<<Tn, 256>>>(x, nm_w + l * Dm, hh, hl);

        GB3 gu;
        gu.w0 = wg + oF; gu.s0 = gs + l * sFsz; gu.y0 = gate;
        gu.w1 = wu + oF; gu.s1 = us + l * sFsz; gu.y1 = up;
        gu.w2 = gu.w1;   gu.s2 = gu.s1;         gu.y2 = up;
        gemm_batch<<<gGU, 512, GEMM_SMEM>>>(hh, hl, gu, FFm, Dm);

        long n4 = (long)Tn * FFm / 4;
        silu_mul_kernel<<<(unsigned)((n4 + 255) / 256), 256>>>(gate, up, gh, gl, n4);

        gemm_kernel<<<gD, 512, GEMM_SMEM>>>(gh, gl, wd + oF, ds + l * sFsz,
                                            x, x, Dm, FFm);
    }

    rms_kernel<<<Tn, 256>>>(x, nf_w, hh, hl);
    gemm_kernel<<<gVg, 512, GEMM_SMEM>>>(hh, hl, wh, head_s, nullptr,
                                         (float*)d_out, Vv, Dm);
}

// round 9
// speedup vs baseline: 1.1706x; 1.1706x over previous
#include <cuda_runtime.h>
#include <cuda_bf16.h>
#include <math.h>
#include <stdint.h>

#define Tn  2048
#define Dm  1024
#define FFm 4096
#define Vv  32000
#define Bm  2
#define Sm  1024
#define Hm  16
#define Lm  6

typedef __nv_bfloat16 bf16;

// ---------------- scratch (static device globals; no allocation) ------------
__device__ float g_x  [Tn * Dm];
__device__ bf16  g_hh [Tn * Dm];
__device__ bf16  g_hl [Tn * Dm];
__device__ float g_q  [Tn * Dm];
__device__ float g_k  [Tn * Dm];
__device__ float g_v  [Tn * Dm];
__device__ bf16  g_ah [Tn * Dm];
__device__ bf16  g_al [Tn * Dm];
__device__ float g_gate[(long)Tn * FFm];
__device__ float g_up  [(long)Tn * FFm];
__device__ bf16  g_gh [(long)Tn * FFm];
__device__ bf16  g_gl [(long)Tn * FFm];

// bf16 ternary weight caches
__device__ bf16 g_wq[(long)Lm * Dm * Dm];
__device__ bf16 g_wk[(long)Lm * Dm * Dm];
__device__ bf16 g_wv[(long)Lm * Dm * Dm];
__device__ bf16 g_wo[(long)Lm * Dm * Dm];
__device__ bf16 g_wg[(long)Lm * FFm * Dm];
__device__ bf16 g_wu[(long)Lm * FFm * Dm];
__device__ bf16 g_wd[(long)Lm * FFm * Dm];
__device__ bf16 g_wh[(long)Vv * Dm];

__device__ __forceinline__ void split_bf16(float v, bf16& hi, bf16& lo) {
    hi = __float2bfloat16(v);
    lo = __float2bfloat16(v - __bfloat162float(hi));
}
__device__ __forceinline__ void cp_async16(uint32_t dst, const void* src) {
    asm volatile("cp.async.cg.shared.global [%0], [%1], 16;" :: "r"(dst), "l"(src));
}
__device__ __forceinline__ void cp_async4(uint32_t dst, const void* src) {
    asm volatile("cp.async.ca.shared.global [%0], [%1], 4;" :: "r"(dst), "l"(src));
}
__device__ __forceinline__ void cp_commit() {
    asm volatile("cp.async.commit_group;");
}
__device__ __forceinline__ uint32_t smem_u32(const void* p) {
    return (uint32_t)__cvta_generic_to_shared(p);
}
__device__ __forceinline__ void ldsm_x4(uint32_t* r, uint32_t addr) {
    asm volatile("ldmatrix.sync.aligned.m8n8.x4.shared.b16 {%0,%1,%2,%3}, [%4];"
                 : "=r"(r[0]), "=r"(r[1]), "=r"(r[2]), "=r"(r[3]) : "r"(addr));
}
__device__ __forceinline__ void mma_bf16(float* d, const uint32_t* a,
                                         const uint32_t* b) {
    asm volatile(
        "mma.sync.aligned.m16n8k16.row.col.f32.bf16.bf16.f32 "
        "{%0,%1,%2,%3}, {%4,%5,%6,%7}, {%8,%9}, {%0,%1,%2,%3};"
        : "+f"(d[0]), "+f"(d[1]), "+f"(d[2]), "+f"(d[3])
        : "r"(a[0]), "r"(a[1]), "r"(a[2]), "r"(a[3]), "r"(b[0]), "r"(b[1]));
}

// ---------------- single-launch weight fp32 -> bf16 --------------------------
struct WAll {
    const float* src[8];
    bf16*        dst[8];
    long         cum[9];
};
__global__ void w2b_all_kernel(WAll wa) {
    long i4 = (long)blockIdx.x * blockDim.x + threadIdx.x;
    if (i4 >= wa.cum[8]) return;
    int seg = 0;
    #pragma unroll
    for (int s = 0; s < 7; s++) if (i4 >= wa.cum[s + 1]) seg = s + 1;
    long li = (i4 - wa.cum[seg]) * 4;
    float4 v = *(const float4*)&wa.src[seg][li];
    bf16* d = wa.dst[seg];
    *(__nv_bfloat162*)&d[li]     = __floats2bfloat162_rn(v.x, v.y);
    *(__nv_bfloat162*)&d[li + 2] = __floats2bfloat162_rn(v.z, v.w);
}

// ---------------- embedding + positional ------------------------------------
__global__ void embed_kernel(const int* __restrict__ ids,
                             const float* __restrict__ et,
                             const float* __restrict__ es,
                             const float* __restrict__ pe,
                             float* __restrict__ x) {
    int t  = blockIdx.x;
    int id = ids[t];
    int s  = t % Sm;
    for (int d = threadIdx.x; d < Dm; d += blockDim.x) {
        long wi = (long)id * Dm + d;
        x[(long)t * Dm + d] = et[wi] * es[wi >> 7] + pe[s * Dm + d];
    }
}

// ---------------- RMSNorm -> hi/lo bf16 --------------------------------------
__global__ void rms_kernel(const float* __restrict__ X,
                           const float* __restrict__ w,
                           bf16* __restrict__ Yh, bf16* __restrict__ Yl) {
    int t = blockIdx.x, tid = threadIdx.x;
    __shared__ float red[256];
    float s = 0.f;
    for (int d = tid; d < Dm; d += 256) {
        float v = X[(long)t * Dm + d];
        s += v * v;
    }
    red[tid] = s; __syncthreads();
    for (int o = 128; o > 0; o >>= 1) {
        if (tid < o) red[tid] += red[tid + o];
        __syncthreads();
    }
    float r = rsqrtf(red[0] / Dm + 1e-6f);
    for (int d = tid; d < Dm; d += 256) {
        float v = X[(long)t * Dm + d] * r * w[d];
        bf16 hi, lo; split_bf16(v, hi, lo);
        Yh[(long)t * Dm + d] = hi;
        Yl[(long)t * Dm + d] = lo;
    }
}

// ---------------- 2-pass GEMM, 128x128 tile, smem-cached scales --------------
#define SAS 72
#define A_ELE (128 * SAS)
#define STAGE_E (3 * A_ELE)                                  // Ah, Al, W
#define MAXG 32                                              // max groups (IN=4096)
#define GEMM_SMEM (2 * STAGE_E * (int)sizeof(bf16) + MAXG * 128 * (int)sizeof(float))

__device__ __forceinline__ void gemm_core(const bf16* __restrict__ Xh,
                                          const bf16* __restrict__ Xl,
                                          const bf16* __restrict__ W,
                                          const float* __restrict__ Sc,
                                          const float* __restrict__ res,
                                          float* __restrict__ Y,
                                          int R, int IN, int bm, int bn) {
    extern __shared__ bf16 smp[];
    float* sSc = (float*)(smp + 2 * STAGE_E);   // [groups][128]

    const int tid  = threadIdx.x;
    const int warp = tid >> 5, lane = tid & 31;
    const int warpM = warp & 3, warpN = warp >> 2;
    const int groups = IN >> 7;
    const int lr = lane >> 2;
    const int lc = (lane & 3) << 1;
    const int lrow  = lane & 15;
    const int lcol8 = (lane >> 4) << 3;

    float master[2][4][4];
    float temp  [2][4][4];
    #pragma unroll
    for (int a = 0; a < 2; a++)
        #pragma unroll
        for (int b = 0; b < 4; b++)
            #pragma unroll
            for (int c = 0; c < 4; c++) { master[a][b][c] = 0.f; temp[a][b][c] = 0.f; }

    const int nIter = IN >> 6;

    auto load_stage = [&](int st, int it) {
        bf16* ah = smp + st * STAGE_E;
        bf16* al = ah + A_ELE;
        bf16* ws = al + A_ELE;
        int k0 = it << 6;
        #pragma unroll
        for (int p = 0; p < 2; p++) {
            int idx = tid + p * 512;
            int m = idx >> 3, c8 = (idx & 7) << 3;
            long gi = (long)(bm + m) * IN + k0 + c8;
            cp_async16(smem_u32(ah + m * SAS + c8), Xh + gi);
            cp_async16(smem_u32(al + m * SAS + c8), Xl + gi);
            cp_async16(smem_u32(ws + m * SAS + c8), W + (long)(bn + m) * IN + k0 + c8);
        }
    };

    // stage 0 + all scales in commit group 0
    load_stage(0, 0);
    for (int idx = tid; idx < groups * 128; idx += 512) {
        int rl = idx & 127, g = idx >> 7;
        cp_async4(smem_u32(sSc + idx), Sc + (long)(bn + rl) * groups + g);
    }
    cp_commit();

    for (int it = 0; it < nIter; it++) {
        if (it + 1 < nIter) {
            load_stage((it + 1) & 1, it + 1);
            cp_commit();
            asm volatile("cp.async.wait_group 1;");
        } else {
            asm volatile("cp.async.wait_group 0;");
        }
        __syncthreads();

        const int st = it & 1;
        const bf16* ah = smp + st * STAGE_E;
        const bf16* al = ah + A_ELE;
        const bf16* ws = al + A_ELE;

        #pragma unroll
        for (int ks = 0; ks < 4; ks++) {
            const int kb = ks * 16;
            uint32_t fah[2][4], fal[2][4], fb[4][2];
            #pragma unroll
            for (int mt = 0; mt < 2; mt++) {
                int m0 = warpM * 32 + mt * 16;
                ldsm_x4(fah[mt], smem_u32(ah + (m0 + lrow) * SAS + kb + lcol8));
                ldsm_x4(fal[mt], smem_u32(al + (m0 + lrow) * SAS + kb + lcol8));
            }
            #pragma unroll
            for (int np = 0; np < 2; np++) {
                int n0 = warpN * 32 + np * 16;
                uint32_t q[4];
                ldsm_x4(q, smem_u32(ws + (n0 + lrow) * SAS + kb + lcol8));
                fb[np * 2][0] = q[0];     fb[np * 2][1] = q[2];
                fb[np * 2 + 1][0] = q[1]; fb[np * 2 + 1][1] = q[3];
            }
            #pragma unroll
            for (int mt = 0; mt < 2; mt++)
                #pragma unroll
                for (int nt = 0; nt < 4; nt++) {
                    mma_bf16(temp[mt][nt], fah[mt], fb[nt]);
                    mma_bf16(temp[mt][nt], fal[mt], fb[nt]);
                }
        }

        if (it & 1) {   // 128-K group boundary: fold with smem-cached scales
            int g = it >> 1;
            #pragma unroll
            for (int nt = 0; nt < 4; nt++) {
                int rl = warpN * 32 + nt * 8 + lc;
                float s0 = sSc[g * 128 + rl];
                float s1 = sSc[g * 128 + rl + 1];
                #pragma unroll
                for (int mt = 0; mt < 2; mt++) {
                    master[mt][nt][0] += s0 * temp[mt][nt][0];
                    master[mt][nt][1] += s1 * temp[mt][nt][1];
                    master[mt][nt][2] += s0 * temp[mt][nt][2];
                    master[mt][nt][3] += s1 * temp[mt][nt][3];
                    temp[mt][nt][0] = 0.f; temp[mt][nt][1] = 0.f;
                    temp[mt][nt][2] = 0.f; temp[mt][nt][3] = 0.f;
                }
            }
        }
        __syncthreads();
    }

    #pragma unroll
    for (int mt = 0; mt < 2; mt++) {
        int m0 = bm + warpM * 32 + mt * 16 + lr;
        #pragma unroll
        for (int nt = 0; nt < 4; nt++) {
            int r0 = bn + warpN * 32 + nt * 8 + lc;
            float2 v0 = make_float2(master[mt][nt][0], master[mt][nt][1]);
            float2 v1 = make_float2(master[mt][nt][2], master[mt][nt][3]);
            if (res) {
                float2 p0 = *(const float2*)&res[(long)m0 * R + r0];
                float2 p1 = *(const float2*)&res[(long)(m0 + 8) * R + r0];
                v0.x += p0.x; v0.y += p0.y;
                v1.x += p1.x; v1.y += p1.y;
            }
            *(float2*)&Y[(long)m0 * R + r0]       = v0;
            *(float2*)&Y[(long)(m0 + 8) * R + r0] = v1;
        }
    }
}

__global__ void __launch_bounds__(512)
gemm_kernel(const bf16* __restrict__ Xh, const bf16* __restrict__ Xl,
            const bf16* __restrict__ W, const float* __restrict__ Sc,
            const float* __restrict__ res, float* __restrict__ Y,
            int R, int IN) {
    gemm_core(Xh, Xl, W, Sc, res, Y, R, IN, blockIdx.y * 128, blockIdx.x * 128);
}

struct GB3 {
    const bf16 *w0, *w1, *w2;
    const float *s0, *s1, *s2;
    float *y0, *y1, *y2;
};
__global__ void __launch_bounds__(512)
gemm_batch(const bf16* __restrict__ Xh, const bf16* __restrict__ Xl,
           GB3 gb, int R, int IN) {
    int z = blockIdx.z;
    const bf16*  W  = (z == 0) ? gb.w0 : (z == 1) ? gb.w1 : gb.w2;
    const float* Sc = (z == 0) ? gb.s0 : (z == 1) ? gb.s1 : gb.s2;
    float*       Y  = (z == 0) ? gb.y0 : (z == 1) ? gb.y1 : gb.y2;
    gemm_core(Xh, Xl, W, Sc, nullptr, Y, R, IN, blockIdx.y * 128, blockIdx.x * 128);
}

// ---------------- balanced flash attention (stride-65, conflict-free) --------
#define ATTN_SMEM (4 * 64 * 65 * (int)sizeof(float))

__global__ void __launch_bounds__(128)
attn_flash_kernel(const float* __restrict__ Q,
                  const float* __restrict__ K,
                  const float* __restrict__ V,
                  const bf16* __restrict__ Hh,
                  const bf16* __restrict__ Hl,
                  const float* __restrict__ alpha,
                  int layer,
                  bf16* __restrict__ Oh, bf16* __restrict__ Ol) {
    extern __shared__ float sm[];
    float* sQ = sm;
    float* sK = sm + 64 * 65;
    float* sV = sm + 2 * 64 * 65;
    float* sP = sm + 3 * 64 * 65;

    const int nQT = Sm / 64;
    const int h = blockIdx.y, b = blockIdx.z;
    const int tid = threadIdx.x, w = tid >> 5, ln = tid & 31;
    const int ry = ln >> 3, cx = ln & 7;
    const int row0 = w * 16 + ry * 4;
    const int hoff = h * 64;

    #pragma unroll
    for (int pass = 0; pass < 2; pass++) {
        const int qt = (pass == 0) ? blockIdx.x : (nQT - 1 - blockIdx.x);
        const long tok0 = (long)b * Sm + qt * 64;

        __syncthreads();
        for (int i = tid; i < 64 * 16; i += 128) {
            int r = i >> 4, c4 = (i & 15) << 2;
            float4 v4 = *(const float4*)&Q[(tok0 + r) * Dm + hoff + c4];
            sQ[r * 65 + c4 + 0] = v4.x; sQ[r * 65 + c4 + 1] = v4.y;
            sQ[r * 65 + c4 + 2] = v4.z; sQ[r * 65 + c4 + 3] = v4.w;
        }

        float m[4], l[4], acc[4][8];
        #pragma unroll
        for (int r = 0; r < 4; r++) {
            m[r] = -1e30f; l[r] = 0.f;
            #pragma unroll
            for (int d = 0; d < 8; d++) acc[r][d] = 0.f;
        }

        const int nkt = qt + 1;
        for (int kt = 0; kt < nkt; kt++) {
            __syncthreads();
            long kbase = (long)b * Sm + kt * 64;
            for (int i = tid; i < 64 * 16; i += 128) {
                int r = i >> 4, c4 = (i & 15) << 2;
                float4 k4 = *(const float4*)&K[(kbase + r) * Dm + hoff + c4];
                sK[r * 65 + c4 + 0] = k4.x; sK[r * 65 + c4 + 1] = k4.y;
                sK[r * 65 + c4 + 2] = k4.z; sK[r * 65 + c4 + 3] = k4.w;
                float4 v4 = *(const float4*)&V[(kbase + r) * Dm + hoff + c4];
                sV[r * 65 + c4 + 0] = v4.x; sV[r * 65 + c4 + 1] = v4.y;
                sV[r * 65 + c4 + 2] = v4.z; sV[r * 65 + c4 + 3] = v4.w;
            }
            __syncthreads();

            float s[4][8];
            #pragma unroll
            for (int r = 0; r < 4; r++)
                #pragma unroll
                for (int c = 0; c < 8; c++) s[r][c] = 0.f;
            for (int d = 0; d < 64; d++) {
                float qv[4], kv[8];
                #pragma unroll
                for (int r = 0; r < 4; r++) qv[r] = sQ[(row0 + r) * 65 + d];
                #pragma unroll
                for (int c = 0; c < 8; c++) kv[c] = sK[(cx * 8 + c) * 65 + d];
                #pragma unroll
                for (int r = 0; r < 4; r++)
                    #pragma unroll
                    for (int c = 0; c < 8; c++)
                        s[r][c] = fmaf(qv[r], kv[c], s[r][c]);
            }
            const bool diag = (kt == qt);
            #pragma unroll
            for (int r = 0; r < 4; r++)
                #pragma unroll
                for (int c = 0; c < 8; c++) {
                    s[r][c] *= 0.125f;
                    if (diag && (cx * 8 + c > row0 + r)) s[r][c] = -1e30f;
                }

            #pragma unroll
            for (int r = 0; r < 4; r++) {
                float mn = s[r][0];
                #pragma unroll
                for (int c = 1; c < 8; c++) mn = fmaxf(mn, s[r][c]);
                #pragma unroll
                for (int o = 1; o < 8; o <<= 1)
                    mn = fmaxf(mn, __shfl_xor_sync(0xffffffffu, mn, o));
                mn = fmaxf(mn, m[r]);
                float fac = expf(m[r] - mn);
                m[r] = mn;
                float ls = 0.f;
                #pragma unroll
                for (int c = 0; c < 8; c++) {
                    float p = expf(s[r][c] - mn);
                    sP[(row0 + r) * 65 + cx * 8 + c] = p;
                    ls += p;
                }
                #pragma unroll
                for (int o = 1; o < 8; o <<= 1)
                    ls += __shfl_xor_sync(0xffffffffu, ls, o);
                l[r] = l[r] * fac + ls;
                #pragma unroll
                for (int d = 0; d < 8; d++) acc[r][d] *= fac;
            }
            __syncwarp();

            for (int j = 0; j < 64; j++) {
                float pv[4], vv[8];
                #pragma unroll
                for (int r = 0; r < 4; r++) pv[r] = sP[(row0 + r) * 65 + j];
                #pragma unroll
                for (int d = 0; d < 8; d++) vv[d] = sV[j * 65 + cx * 8 + d];
                #pragma unroll
                for (int r = 0; r < 4; r++)
                    #pragma unroll
                    for (int d = 0; d < 8; d++)
                        acc[r][d] = fmaf(pv[r], vv[d], acc[r][d]);
            }
            __syncwarp();
        }

        float a = alpha[layer * Hm + h];
        #pragma unroll
        for (int r = 0; r < 4; r++) {
            float inv = 1.f / l[r];
            long t = tok0 + row0 + r;
            #pragma unroll
            for (int d = 0; d < 8; d++) {
                long oi = t * Dm + hoff + cx * 8 + d;
                float hn = __bfloat162float(Hh[oi]) + __bfloat162float(Hl[oi]);
                float v = acc[r][d] * inv + a * hn;
                bf16 hi, lo; split_bf16(v, hi, lo);
                Oh[oi] = hi; Ol[oi] = lo;
            }
        }
    }
}

// ---------------- SiLU(gate) * up -> hi/lo bf16 (float4) ---------------------
__global__ void silu_mul_kernel(const float* __restrict__ g,
                                const float* __restrict__ u,
                                bf16* __restrict__ Yh, bf16* __restrict__ Yl,
                                long n4) {
    long i = ((long)blockIdx.x * blockDim.x + threadIdx.x);
    if (i < n4) {
        long b = i * 4;
        float4 gv = *(const float4*)&g[b];
        float4 uv = *(const float4*)&u[b];
        float v0 = (gv.x / (1.f + expf(-gv.x))) * uv.x;
        float v1 = (gv.y / (1.f + expf(-gv.y))) * uv.y;
        float v2 = (gv.z / (1.f + expf(-gv.z))) * uv.z;
        float v3 = (gv.w / (1.f + expf(-gv.w))) * uv.w;
        bf16 h0, l0, h1, l1, h2, l2, h3, l3;
        split_bf16(v0, h0, l0); split_bf16(v1, h1, l1);
        split_bf16(v2, h2, l2); split_bf16(v3, h3, l3);
        *(__nv_bfloat162*)&Yh[b]     = __nv_bfloat162(h0, h1);
        *(__nv_bfloat162*)&Yh[b + 2] = __nv_bfloat162(h2, h3);
        *(__nv_bfloat162*)&Yl[b]     = __nv_bfloat162(l0, l1);
        *(__nv_bfloat162*)&Yl[b + 2] = __nv_bfloat162(l2, l3);
    }
}

// =============================================================================
extern "C" void kernel_launch(void* const* d_in, const int* in_sizes, int n_in,
                              void* d_out, int out_size) {
    const int*   ids    = (const int*)  d_in[0];
    const float* emb_t  = (const float*)d_in[1];
    const float* emb_s  = (const float*)d_in[2];
    const float* pos    = (const float*)d_in[3];
    const float* q_t    = (const float*)d_in[4];
    const float* q_s    = (const float*)d_in[5];
    const float* k_t    = (const float*)d_in[6];
    const float* k_s    = (const float*)d_in[7];
    const float* v_t    = (const float*)d_in[8];
    const float* v_s    = (const float*)d_in[9];
    const float* o_t    = (const float*)d_in[10];
    const float* o_s    = (const float*)d_in[11];
    const float* gt     = (const float*)d_in[12];
    const float* gs     = (const float*)d_in[13];
    const float* ut     = (const float*)d_in[14];
    const float* us     = (const float*)d_in[15];
    const float* dt     = (const float*)d_in[16];
    const float* ds     = (const float*)d_in[17];
    const float* alpha  = (const float*)d_in[18];
    const float* na_w   = (const float*)d_in[19];
    const float* nm_w   = (const float*)d_in[20];
    const float* nf_w   = (const float*)d_in[21];
    const float* head_t = (const float*)d_in[22];
    const float* head_s = (const float*)d_in[23];

    float *x, *q, *k, *v, *gate, *up;
    bf16 *hh, *hl, *ah, *al, *gh, *gl;
    bf16 *wq, *wk, *wv, *wo, *wg, *wu, *wd, *wh;
    cudaGetSymbolAddress((void**)&x,    g_x);
    cudaGetSymbolAddress((void**)&hh,   g_hh);
    cudaGetSymbolAddress((void**)&hl,   g_hl);
    cudaGetSymbolAddress((void**)&q,    g_q);
    cudaGetSymbolAddress((void**)&k,    g_k);
    cudaGetSymbolAddress((void**)&v,    g_v);
    cudaGetSymbolAddress((void**)&ah,   g_ah);
    cudaGetSymbolAddress((void**)&al,   g_al);
    cudaGetSymbolAddress((void**)&gate, g_gate);
    cudaGetSymbolAddress((void**)&up,   g_up);
    cudaGetSymbolAddress((void**)&gh,   g_gh);
    cudaGetSymbolAddress((void**)&gl,   g_gl);
    cudaGetSymbolAddress((void**)&wq,   g_wq);
    cudaGetSymbolAddress((void**)&wk,   g_wk);
    cudaGetSymbolAddress((void**)&wv,   g_wv);
    cudaGetSymbolAddress((void**)&wo,   g_wo);
    cudaGetSymbolAddress((void**)&wg,   g_wg);
    cudaGetSymbolAddress((void**)&wu,   g_wu);
    cudaGetSymbolAddress((void**)&wd,   g_wd);
    cudaGetSymbolAddress((void**)&wh,   g_wh);

    const long sQsz = (long)Dm * Dm / 128;
    const long sFsz = (long)Dm * FFm / 128;
    const long nD = (long)Lm * Dm * Dm;
    const long nF = (long)Lm * FFm * Dm;
    const long nH = (long)Vv * Dm;

    static bool attr_done = false;
    if (!attr_done) {
        cudaFuncSetAttribute(gemm_kernel,
                             cudaFuncAttributeMaxDynamicSharedMemorySize, GEMM_SMEM);
        cudaFuncSetAttribute(gemm_batch,
                             cudaFuncAttributeMaxDynamicSharedMemorySize, GEMM_SMEM);
        cudaFuncSetAttribute(attn_flash_kernel,
                             cudaFuncAttributeMaxDynamicSharedMemorySize, ATTN_SMEM);
        attr_done = true;
    }

    // ---- single-launch weight conversion ----
    {
        WAll wa;
        const float* srcs[8] = {q_t, k_t, v_t, o_t, gt, ut, dt, head_t};
        bf16* dsts[8]        = {wq,  wk,  wv,  wo,  wg, wu, wd, wh};
        long  szs[8]         = {nD,  nD,  nD,  nD,  nF, nF, nF, nH};
        long c = 0;
        wa.cum[0] = 0;
        for (int i = 0; i < 8; i++) {
            wa.src[i] = srcs[i]; wa.dst[i] = dsts[i];
            c += szs[i] / 4; wa.cum[i + 1] = c;
        }
        w2b_all_kernel<<<(unsigned)((c + 255) / 256), 256>>>(wa);
    }

    embed_kernel<<<Tn, 256>>>(ids, emb_t, emb_s, pos, x);

    dim3 gD(Dm / 128,  Tn / 128);        // 128
    dim3 gQKV(Dm / 128, Tn / 128, 3);    // 384
    dim3 gGU(FFm / 128, Tn / 128, 2);    // 1024
    dim3 gVg(Vv / 128, Tn / 128);        // 4000
    dim3 ga(Sm / 128, Hm, Bm);           // 256 balanced blocks

    for (int l = 0; l < Lm; l++) {
        long oD = (long)l * Dm * Dm;
        long oF = (long)l * FFm * Dm;

        rms_kernel<<<Tn, 256>>>(x, na_w + l * Dm, hh, hl);

        GB3 qkv;
        qkv.w0 = wq + oD; qkv.s0 = q_s + l * sQsz; qkv.y0 = q;
        qkv.w1 = wk + oD; qkv.s1 = k_s + l * sQsz; qkv.y1 = k;
        qkv.w2 = wv + oD; qkv.s2 = v_s + l * sQsz; qkv.y2 = v;
        gemm_batch<<<gQKV, 512, GEMM_SMEM>>>(hh, hl, qkv, Dm, Dm);

        attn_flash_kernel<<<ga, 128, ATTN_SMEM>>>(q, k, v, hh, hl, alpha, l, ah, al);

        gemm_kernel<<<gD, 512, GEMM_SMEM>>>(ah, al, wo + oD, o_s + l * sQsz,
                                            x, x, Dm, Dm);

        rms_kernel<<<Tn, 256>>>(x, nm_w + l * Dm, hh, hl);

        GB3 gu;
        gu.w0 = wg + oF; gu.s0 = gs + l * sFsz; gu.y0 = gate;
        gu.w1 = wu + oF; gu.s1 = us + l * sFsz; gu.y1 = up;
        gu.w2 = gu.w1;   gu.s2 = gu.s1;         gu.y2 = up;
        gemm_batch<<<gGU, 512, GEMM_SMEM>>>(hh, hl, gu, FFm, Dm);

        long n4 = (long)Tn * FFm / 4;
        silu_mul_kernel<<<(unsigned)((n4 + 255) / 256), 256>>>(gate, up, gh, gl, n4);

        gemm_kernel<<<gD, 512, GEMM_SMEM>>>(gh, gl, wd + oF, ds + l * sFsz,
                                            x, x, Dm, FFm);
    }

    rms_kernel<<<Tn, 256>>>(x, nf_w, hh, hl);
    gemm_kernel<<<gVg, 512, GEMM_SMEM>>>(hh, hl, wh, head_s, nullptr,
                                         (float*)d_out, Vv, Dm);
}